// round 1
// baseline (speedup 1.0000x reference)
#include <cuda_runtime.h>
#include <cstdint>

#define B_ROWS 16384
#define DIM    256
#define BD     (B_ROWS * DIM)
#define LSTEPS 6
#define NFX    8
#define HG     0.005f   /* GAMMA / 2 */

// ---------------- device scratch (static: no runtime allocation) ----------------
__device__ float g_p[BD];        // sigma(az)
__device__ float g_q[BD];        // sigma(az)/softplus(az)
__device__ float g_s[BD];        // softplus(az)
__device__ float g_u[BD];        // -0.5*sigma(a(vh))/softplus(a(vh))
__device__ float g_c[BD];        // HG*(s(az)*vh + 2*r)
__device__ float g_WT[DIM * DIM];

typedef unsigned long long ull;

// ---------------- packed fp32x2 helpers (sm_100+) ----------------
__device__ __forceinline__ ull pack2(float x) {
    ull r; asm("mov.b64 %0, {%1, %1};" : "=l"(r) : "f"(x)); return r;
}
__device__ __forceinline__ void unpack2(ull p, float &lo, float &hi) {
    asm("mov.b64 {%0, %1}, %2;" : "=f"(lo), "=f"(hi) : "l"(p));
}
__device__ __forceinline__ void fma2(ull &d, ull a, ull b) {
    asm("fma.rn.f32x2 %0, %1, %2, %0;" : "+l"(d) : "l"(a), "l"(b));
}

// ---------------- stable sigmoid / softplus ----------------
__device__ __forceinline__ void sig_sp(float x, float &sg, float &sp) {
    float ax  = fabsf(x);
    float e   = expf(-ax);          // in (0,1]
    float l   = log1pf(e);
    sp        = (x > 0.f) ? (x + l) : l;
    float inv = 1.f / (1.f + e);    // sigmoid(|x|)
    sg        = (x > 0.f) ? inv : (1.f - inv);
}
__device__ __forceinline__ float softplus1(float x) {
    float ax = fabsf(x);
    float l  = log1pf(expf(-ax));
    return (x > 0.f) ? (x + l) : l;
}

// ---------------- modes ----------------
#define MODE_A     0   // Y = z@W+bias  -> store p=sigma, q=sigma/s, s
#define MODE_VLOOP 1   // Y = g(p,q,v)@WT        -> v -= HG*Y
#define MODE_U     2   // Y = v@W+bias           -> u = -0.5*sigma(Y)/s(Y)
#define MODE_C     3   // Y = u@WT  (=r)         -> c = HG*(s*v + 2*Y)
#define MODE_Z     4   // Y = z@W+bias           -> z += c + HG*softplus(Y)*v

// ---------------- fused GEMM: C[16384x256] = A[16384x256] * B[256x256] ----------------
// BM=64, BN=256 (full row owned by one CTA -> in-place row updates are safe),
// BK=32, 256 threads, per-thread tile 4 rows x 16 cols (8 f32x2 accum pairs x 4 rows).
template <int MODE>
__global__ __launch_bounds__(256, 2)
void gemm_k(const float* __restrict__ W, const float* __restrict__ bias,
            float* __restrict__ z, float* __restrict__ v)
{
    constexpr bool HAS_BIAS = (MODE == MODE_A || MODE == MODE_U || MODE == MODE_Z);
    const float* __restrict__ Bmat = (MODE == MODE_VLOOP || MODE == MODE_C) ? g_WT : W;

    __shared__ float As[64][33];    // padded: conflict-free
    __shared__ float Bs[32][256];

    const int tid = threadIdx.x;
    const int tx  = tid & 15;       // 16 col-groups
    const int ty  = tid >> 4;       // 16 row-groups
    const int m0  = blockIdx.x * 64;

    ull acc[4][8];
#pragma unroll
    for (int r = 0; r < 4; r++)
#pragma unroll
        for (int c = 0; c < 8; c++) acc[r][c] = 0ull;

    const int ak = tid & 31, ar = tid >> 5;          // A loader: 32 k-lanes x 8 row-lanes
    const int bc = (tid & 63) * 4, br = tid >> 6;    // B loader: 64 float4-lanes x 4 row-lanes

    for (int kt = 0; kt < 8; kt++) {
        const int k0 = kt * 32;
        // ---- A tile (with on-the-fly transform for VLOOP) ----
#pragma unroll
        for (int ii = 0; ii < 8; ii++) {
            int row = ar + ii * 8;
            int gi  = (m0 + row) * DIM + k0 + ak;
            float a;
            if (MODE == MODE_VLOOP) {
                float vv = v[gi];
                a = 0.5f * (g_p[gi] * vv * vv - g_q[gi]);
            } else if (MODE == MODE_U) {
                a = v[gi];
            } else if (MODE == MODE_C) {
                a = g_u[gi];
            } else {                      // MODE_A, MODE_Z
                a = z[gi];
            }
            As[row][ak] = a;
        }
        // ---- B tile ----
#pragma unroll
        for (int ii = 0; ii < 8; ii++) {
            int kk = br + ii * 4;
            *(float4*)&Bs[kk][bc] = *(const float4*)&Bmat[(k0 + kk) * DIM + bc];
        }
        __syncthreads();
        // ---- compute ----
#pragma unroll
        for (int k = 0; k < 32; k++) {
            ull ap[4];
#pragma unroll
            for (int r = 0; r < 4; r++) ap[r] = pack2(As[ty * 4 + r][k]);
            ull bb[8];
#pragma unroll
            for (int cc = 0; cc < 4; cc++) {
                ulonglong2 t = *(const ulonglong2*)&Bs[k][tx * 4 + cc * 64];
                bb[2 * cc] = t.x; bb[2 * cc + 1] = t.y;
            }
#pragma unroll
            for (int r = 0; r < 4; r++)
#pragma unroll
                for (int c = 0; c < 8; c++) fma2(acc[r][c], ap[r], bb[c]);
        }
        __syncthreads();
    }

    // ---- epilogue: thread owns rows m0+ty*4+{0..3}, cols tx*4 + cc*64 + {0..3} ----
#pragma unroll
    for (int r = 0; r < 4; r++) {
        const int row = m0 + ty * 4 + r;
#pragma unroll
        for (int cc = 0; cc < 4; cc++) {
            const int j0 = tx * 4 + cc * 64;
            float ys[4];
            unpack2(acc[r][2 * cc],     ys[0], ys[1]);
            unpack2(acc[r][2 * cc + 1], ys[2], ys[3]);
            if (HAS_BIAS) {
                float4 b4 = *(const float4*)&bias[j0];
                ys[0] += b4.x; ys[1] += b4.y; ys[2] += b4.z; ys[3] += b4.w;
            }
            const int idx = row * DIM + j0;

            if (MODE == MODE_A) {
                float4 p4, q4, s4;
                float sg, ss;
                sig_sp(ys[0], sg, ss); p4.x = sg; q4.x = sg / ss; s4.x = ss;
                sig_sp(ys[1], sg, ss); p4.y = sg; q4.y = sg / ss; s4.y = ss;
                sig_sp(ys[2], sg, ss); p4.z = sg; q4.z = sg / ss; s4.z = ss;
                sig_sp(ys[3], sg, ss); p4.w = sg; q4.w = sg / ss; s4.w = ss;
                *(float4*)&g_p[idx] = p4;
                *(float4*)&g_q[idx] = q4;
                *(float4*)&g_s[idx] = s4;
            } else if (MODE == MODE_VLOOP) {
                float4 vv = *(float4*)&v[idx];
                vv.x -= HG * ys[0]; vv.y -= HG * ys[1];
                vv.z -= HG * ys[2]; vv.w -= HG * ys[3];
                *(float4*)&v[idx] = vv;
            } else if (MODE == MODE_U) {
                float4 u4;
                float sg, ss;
                sig_sp(ys[0], sg, ss); u4.x = -0.5f * sg / ss;
                sig_sp(ys[1], sg, ss); u4.y = -0.5f * sg / ss;
                sig_sp(ys[2], sg, ss); u4.z = -0.5f * sg / ss;
                sig_sp(ys[3], sg, ss); u4.w = -0.5f * sg / ss;
                *(float4*)&g_u[idx] = u4;
            } else if (MODE == MODE_C) {
                float4 s4 = *(float4*)&g_s[idx];
                float4 vv = *(float4*)&v[idx];
                float4 c4;
                c4.x = HG * (s4.x * vv.x + 2.f * ys[0]);
                c4.y = HG * (s4.y * vv.y + 2.f * ys[1]);
                c4.z = HG * (s4.z * vv.z + 2.f * ys[2]);
                c4.w = HG * (s4.w * vv.w + 2.f * ys[3]);
                *(float4*)&g_c[idx] = c4;
            } else { // MODE_Z
                float4 zz = *(float4*)&z[idx];
                float4 c4 = *(float4*)&g_c[idx];
                float4 vv = *(float4*)&v[idx];
                zz.x += c4.x + HG * softplus1(ys[0]) * vv.x;
                zz.y += c4.y + HG * softplus1(ys[1]) * vv.y;
                zz.z += c4.z + HG * softplus1(ys[2]) * vv.z;
                zz.w += c4.w + HG * softplus1(ys[3]) * vv.w;
                *(float4*)&z[idx] = zz;
            }
        }
    }
}

// ---------------- init: z=z0, v=v0 ----------------
__global__ void init_k(float* __restrict__ z, float* __restrict__ v,
                       const float* __restrict__ z0, const float* __restrict__ v0)
{
    const float4* a = (const float4*)z0;
    const float4* b = (const float4*)v0;
    float4* zz = (float4*)z;
    float4* vv = (float4*)v;
    for (int i = blockIdx.x * blockDim.x + threadIdx.x; i < BD / 4;
         i += gridDim.x * blockDim.x) {
        zz[i] = a[i];
        vv[i] = b[i];
    }
}

// ---------------- W transpose (so both GEMM orientations are K-major) ----------------
__global__ void transpose_k(const float* __restrict__ W)
{
    __shared__ float t[32][33];
    const int bx = blockIdx.x * 32, by = blockIdx.y * 32;
    const int x = threadIdx.x, y = threadIdx.y;   // block 32x8
#pragma unroll
    for (int j = 0; j < 32; j += 8)
        t[y + j][x] = W[(by + y + j) * DIM + bx + x];
    __syncthreads();
#pragma unroll
    for (int j = 0; j < 32; j += 8)
        g_WT[(bx + y + j) * DIM + by + x] = t[x][y + j];
}

// ---------------- host launch sequence (graph-capturable: launches only) ----------------
extern "C" void kernel_launch(void* const* d_in, const int* in_sizes, int n_in,
                              void* d_out, int out_size)
{
    // Robust input identification by size
    const float* z0 = nullptr; const float* v0 = nullptr;
    const float* W  = nullptr; const float* bias = nullptr;
    for (int i = 0; i < n_in; i++) {
        if (in_sizes[i] == BD) {
            if (!z0) z0 = (const float*)d_in[i];
            else if (!v0) v0 = (const float*)d_in[i];
        } else if (in_sizes[i] == DIM * DIM) {
            W = (const float*)d_in[i];
        } else if (in_sizes[i] == DIM) {
            bias = (const float*)d_in[i];
        }
    }

    float* z = (float*)d_out;          // out[0] = z_f
    float* v = z + BD;                 // out[1] = v_f

    init_k<<<1024, 256>>>(z, v, z0, v0);
    transpose_k<<<dim3(8, 8), dim3(32, 8)>>>(W);

    const dim3 g(B_ROWS / 64), t(256);

    // az-derived coefficients at z0
    gemm_k<MODE_A><<<g, t>>>(W, bias, z, v);

    for (int s = 0; s < LSTEPS; s++) {
        // implicit velocity half-step: vh_{k+1} = vh_k - HG * (g(vh_k) @ WT)
        for (int i = 0; i < NFX; i++) gemm_k<MODE_VLOOP><<<g, t>>>(W, bias, z, v);
        // r = u @ WT with u from a(vh); then c = HG*(s(az)*vh + 2r)
        gemm_k<MODE_U><<<g, t>>>(W, bias, z, v);
        gemm_k<MODE_C><<<g, t>>>(W, bias, z, v);
        // implicit position step: zn_{k+1} = zn_k + c + HG * s(a(zn_k)) * vh
        for (int i = 0; i < NFX; i++) gemm_k<MODE_Z><<<g, t>>>(W, bias, z, v);
        // refresh az-derived coefficients at z_new, then final velocity half-step
        gemm_k<MODE_A><<<g, t>>>(W, bias, z, v);
        gemm_k<MODE_VLOOP><<<g, t>>>(W, bias, z, v);
    }
    // z, v already live in d_out
}

// round 4
// speedup vs baseline: 1.9583x; 1.9583x over previous
#include <cuda_runtime.h>
#include <cstdint>

#define B_ROWS 16384
#define DIM    256
#define BD     (B_ROWS * DIM)
#define LSTEPS 6
#define NFX    8
#define HG     0.005f   /* GAMMA / 2 */

// ---------------- device scratch ----------------
__device__ float g_p[BD];        // sigma(az)
__device__ float g_q[BD];        // sigma(az)/softplus(az)
__device__ float g_s[BD];        // softplus(az)
__device__ float g_u[BD];        // -0.5*sigma(a(vh))/softplus(a(vh))
__device__ float g_c[BD];        // HG*(s(az)*vh + 2*r)
__device__ float g_WT[DIM * DIM];

// ---------------- stable sigmoid / softplus (fast exp, accurate log1p) ----------------
__device__ __forceinline__ void sig_sp(float x, float &sg, float &sp) {
    float ax  = fabsf(x);
    float e   = __expf(-ax);          // in (0,1]
    float l   = log1pf(e);
    sp        = (x > 0.f) ? (x + l) : l;
    float inv = __fdividef(1.f, 1.f + e);
    sg        = (x > 0.f) ? inv : (1.f - inv);
}
__device__ __forceinline__ float softplus1(float x) {
    float ax = fabsf(x);
    float l  = log1pf(__expf(-ax));
    return (x > 0.f) ? (x + l) : l;
}
// tf32 cvt: destination must be a b32 register ("=r"), bit-pattern is valid fp32
__device__ __forceinline__ float to_tf32(float x) {
    uint32_t y;
    asm("cvt.rna.tf32.f32 %0, %1;" : "=r"(y) : "f"(x));
    return __uint_as_float(y);
}

// ---------------- m16n8k8 tf32 mma ----------------
__device__ __forceinline__ void mma8(float* d, const uint32_t* a, const uint32_t* b) {
    asm volatile(
        "mma.sync.aligned.m16n8k8.row.col.f32.tf32.tf32.f32 "
        "{%0,%1,%2,%3}, {%4,%5,%6,%7}, {%8,%9}, {%0,%1,%2,%3};"
        : "+f"(d[0]), "+f"(d[1]), "+f"(d[2]), "+f"(d[3])
        : "r"(a[0]), "r"(a[1]), "r"(a[2]), "r"(a[3]), "r"(b[0]), "r"(b[1]));
}

// ---------------- modes ----------------
#define MODE_A     0   // Y = z@W+bias  -> p=sigma, q=sigma/s, s
#define MODE_VLOOP 1   // Y = g(p,q,v)@WT -> v -= HG*Y
#define MODE_U     2   // Y = v@W+bias   -> u = -0.5*sigma/s
#define MODE_C     3   // Y = u@WT (=r)  -> c = HG*(s*v + 2*Y)
#define MODE_Z     4   // Y = z@W+bias   -> z += c + HG*softplus(Y)*v

#define AS_STRIDE 36   // bank = (4*row + col) % 32 : conflict-free for frag reads
#define BS_STRIDE 264  // bank = (8*k + n) % 32     : conflict-free for frag reads

// ---------------- fused GEMM: Y[16384x256] = A[16384x256] * Bmat[256x256] ----------------
// BM=64, BN=256, BK=32. 256 threads = 8 warps as 2(m) x 4(n); warp tile 32x64.
template <int MODE>
__global__ __launch_bounds__(256, 2)
void gemm_mma(const float* __restrict__ W, const float* __restrict__ bias,
              float* __restrict__ z, float* __restrict__ v)
{
    const float* __restrict__ Bop = (MODE == MODE_VLOOP || MODE == MODE_C)
                                        ? (const float*)g_WT : W;

    __shared__ float As[64][AS_STRIDE];
    __shared__ float Bs[32][BS_STRIDE];

    const int tid  = threadIdx.x;
    const int warp = tid >> 5;
    const int lane = tid & 31;
    const int wm   = warp >> 2;         // 0..1 : m offset wm*32
    const int wn   = warp & 3;          // 0..3 : n offset wn*64
    const int m0   = blockIdx.x * 64;

    float acc[2][8][4];
#pragma unroll
    for (int mr = 0; mr < 2; mr++)
#pragma unroll
        for (int nj = 0; nj < 8; nj++)
#pragma unroll
            for (int r = 0; r < 4; r++) acc[mr][nj][r] = 0.f;

    const int ak = tid & 31, ar = tid >> 5;          // A loader lanes
    const int bn = (tid & 63) * 4, bk = tid >> 6;    // B loader lanes

    const int r0 = lane >> 2;   // fragment row-in-group
    const int c0 = lane & 3;    // fragment col-in-group

    for (int kt = 0; kt < 8; kt++) {
        const int k0 = kt * 32;
        // ---- A tile (mode transform fused), tf32-converted ----
#pragma unroll
        for (int ii = 0; ii < 8; ii++) {
            int row = ar + ii * 8;
            int gi  = (m0 + row) * DIM + k0 + ak;
            float a;
            if (MODE == MODE_VLOOP) {
                float vv = v[gi];
                a = 0.5f * (g_p[gi] * vv * vv - g_q[gi]);
            } else if (MODE == MODE_U) {
                a = v[gi];
            } else if (MODE == MODE_C) {
                a = g_u[gi];
            } else {                      // MODE_A, MODE_Z
                a = z[gi];
            }
            As[row][ak] = to_tf32(a);
        }
        // ---- B tile (row-major [k][n]), tf32-converted ----
#pragma unroll
        for (int ii = 0; ii < 8; ii++) {
            int kk = bk + ii * 4;
            float4 b4 = *(const float4*)&Bop[(k0 + kk) * DIM + bn];
            b4.x = to_tf32(b4.x); b4.y = to_tf32(b4.y);
            b4.z = to_tf32(b4.z); b4.w = to_tf32(b4.w);
            *(float4*)&Bs[kk][bn] = b4;
        }
        __syncthreads();

        // ---- 4 k8 steps ----
        const float* As_base = &As[wm * 32 + r0][c0];
        const float* Bs_base = &Bs[c0][wn * 64 + r0];
#pragma unroll
        for (int k8 = 0; k8 < 4; k8++) {
            const int kb = k8 * 8;
            uint32_t af[2][4];
#pragma unroll
            for (int mr = 0; mr < 2; mr++) {
                const float* p = As_base + (mr * 16) * AS_STRIDE + kb;
                af[mr][0] = __float_as_uint(p[0]);
                af[mr][1] = __float_as_uint(p[8 * AS_STRIDE]);
                af[mr][2] = __float_as_uint(p[4]);
                af[mr][3] = __float_as_uint(p[8 * AS_STRIDE + 4]);
            }
            uint32_t bf[8][2];
#pragma unroll
            for (int nj = 0; nj < 8; nj++) {
                const float* p = Bs_base + kb * BS_STRIDE + nj * 8;
                bf[nj][0] = __float_as_uint(p[0]);
                bf[nj][1] = __float_as_uint(p[4 * BS_STRIDE]);
            }
#pragma unroll
            for (int mr = 0; mr < 2; mr++)
#pragma unroll
                for (int nj = 0; nj < 8; nj++)
                    mma8(acc[mr][nj], af[mr], bf[nj]);
        }
        __syncthreads();
    }

    // ---------------- epilogue (from registers; each thread owns its cells) ----
    // cell (mr, nj, hi): row = m0 + wm*32 + mr*16 + r0 + hi*8
    //                    cols = wn*64 + nj*8 + 2*c0 + {0,1}
#pragma unroll
    for (int mr = 0; mr < 2; mr++) {
#pragma unroll
        for (int nj = 0; nj < 8; nj++) {
            const int gc = wn * 64 + nj * 8 + 2 * c0;
            float2 bia = make_float2(0.f, 0.f);
            if (MODE == MODE_A || MODE == MODE_U || MODE == MODE_Z)
                bia = *(const float2*)&bias[gc];
#pragma unroll
            for (int hi = 0; hi < 2; hi++) {
                const int row = m0 + wm * 32 + mr * 16 + r0 + hi * 8;
                const int idx = row * DIM + gc;
                float y0 = acc[mr][nj][2 * hi]     + bia.x;
                float y1 = acc[mr][nj][2 * hi + 1] + bia.y;

                if (MODE == MODE_A) {
                    float sg0, ss0, sg1, ss1;
                    sig_sp(y0, sg0, ss0);
                    sig_sp(y1, sg1, ss1);
                    *(float2*)&g_p[idx] = make_float2(sg0, sg1);
                    *(float2*)&g_q[idx] = make_float2(__fdividef(sg0, ss0),
                                                      __fdividef(sg1, ss1));
                    *(float2*)&g_s[idx] = make_float2(ss0, ss1);
                } else if (MODE == MODE_VLOOP) {
                    float2 vv = *(float2*)&v[idx];
                    vv.x -= HG * y0;
                    vv.y -= HG * y1;
                    *(float2*)&v[idx] = vv;
                } else if (MODE == MODE_U) {
                    float sg0, ss0, sg1, ss1;
                    sig_sp(y0, sg0, ss0);
                    sig_sp(y1, sg1, ss1);
                    *(float2*)&g_u[idx] = make_float2(-0.5f * __fdividef(sg0, ss0),
                                                      -0.5f * __fdividef(sg1, ss1));
                } else if (MODE == MODE_C) {
                    float2 s2 = *(float2*)&g_s[idx];
                    float2 vv = *(float2*)&v[idx];
                    *(float2*)&g_c[idx] = make_float2(HG * (s2.x * vv.x + 2.f * y0),
                                                      HG * (s2.y * vv.y + 2.f * y1));
                } else {  // MODE_Z
                    float2 zz = *(float2*)&z[idx];
                    float2 c2 = *(float2*)&g_c[idx];
                    float2 vv = *(float2*)&v[idx];
                    zz.x += c2.x + HG * softplus1(y0) * vv.x;
                    zz.y += c2.y + HG * softplus1(y1) * vv.y;
                    *(float2*)&z[idx] = zz;
                }
            }
        }
    }
}

// ---------------- init: z=z0, v=v0 ----------------
__global__ void init_k(float* __restrict__ z, float* __restrict__ v,
                       const float* __restrict__ z0, const float* __restrict__ v0)
{
    const float4* a = (const float4*)z0;
    const float4* b = (const float4*)v0;
    float4* zz = (float4*)z;
    float4* vv = (float4*)v;
    for (int i = blockIdx.x * blockDim.x + threadIdx.x; i < BD / 4;
         i += gridDim.x * blockDim.x) {
        zz[i] = a[i];
        vv[i] = b[i];
    }
}

// ---------------- W transpose: g_WT[k][n] = W[n][k] ----------------
__global__ void transpose_k(const float* __restrict__ W)
{
    __shared__ float t[32][33];
    const int bx = blockIdx.x * 32, by = blockIdx.y * 32;
    const int x = threadIdx.x, y = threadIdx.y;   // block 32x8
#pragma unroll
    for (int j = 0; j < 32; j += 8)
        t[y + j][x] = W[(by + y + j) * DIM + bx + x];
    __syncthreads();
#pragma unroll
    for (int j = 0; j < 32; j += 8)
        g_WT[(bx + y + j) * DIM + by + x] = t[x][y + j];
}

// ---------------- host launch sequence (graph-capturable) ----------------
extern "C" void kernel_launch(void* const* d_in, const int* in_sizes, int n_in,
                              void* d_out, int out_size)
{
    const float* z0 = nullptr; const float* v0 = nullptr;
    const float* W  = nullptr; const float* bias = nullptr;
    for (int i = 0; i < n_in; i++) {
        if (in_sizes[i] == BD) {
            if (!z0) z0 = (const float*)d_in[i];
            else if (!v0) v0 = (const float*)d_in[i];
        } else if (in_sizes[i] == DIM * DIM) {
            W = (const float*)d_in[i];
        } else if (in_sizes[i] == DIM) {
            bias = (const float*)d_in[i];
        }
    }

    float* z = (float*)d_out;          // out[0] = z_f
    float* v = z + BD;                 // out[1] = v_f

    init_k<<<1024, 256>>>(z, v, z0, v0);
    transpose_k<<<dim3(8, 8), dim3(32, 8)>>>(W);

    const dim3 g(B_ROWS / 64), t(256);

    gemm_mma<MODE_A><<<g, t>>>(W, bias, z, v);

    for (int s = 0; s < LSTEPS; s++) {
        for (int i = 0; i < NFX; i++) gemm_mma<MODE_VLOOP><<<g, t>>>(W, bias, z, v);
        gemm_mma<MODE_U><<<g, t>>>(W, bias, z, v);
        gemm_mma<MODE_C><<<g, t>>>(W, bias, z, v);
        for (int i = 0; i < NFX; i++) gemm_mma<MODE_Z><<<g, t>>>(W, bias, z, v);
        gemm_mma<MODE_A><<<g, t>>>(W, bias, z, v);
        gemm_mma<MODE_VLOOP><<<g, t>>>(W, bias, z, v);
    }
}

// round 6
// speedup vs baseline: 3.1295x; 1.5981x over previous
#include <cuda_runtime.h>
#include <cuda_bf16.h>
#include <cstdint>

#define B_ROWS 16384
#define DIM    256
#define BD     (B_ROWS * DIM)
#define LSTEPS 6
#define NFX    8
#define HG     0.005f   /* GAMMA / 2 */

// ---------------- device scratch ----------------
__device__ float g_p[BD];        // sigma(az)
__device__ float g_q[BD];        // sigma(az)/softplus(az)
__device__ float g_s[BD];        // softplus(az)
__device__ float g_u[BD];        // -0.5*sigma(a(vh))/softplus(a(vh))
__device__ float g_c[BD];        // HG*(s(az)*vh + 2*r)
__device__ float g_WT[DIM * DIM];            // fp32 W^T-as-[k][n] for tf32 singles
__device__ __nv_bfloat16 g_Wbf[DIM * DIM];   // bf16 copy of W  ([n][k] for vloop B)
__device__ __nv_bfloat16 g_WTbf[DIM * DIM];  // bf16 transpose  ([n][k] for zloop B)

// ---------------- stable sigmoid / softplus ----------------
__device__ __forceinline__ void sig_sp(float x, float &sg, float &sp) {
    float ax  = fabsf(x);
    float e   = __expf(-ax);
    float l   = log1pf(e);
    sp        = (x > 0.f) ? (x + l) : l;
    float inv = __fdividef(1.f, 1.f + e);
    sg        = (x > 0.f) ? inv : (1.f - inv);
}
__device__ __forceinline__ float softplus1(float x) {
    float ax = fabsf(x);
    float l  = log1pf(__expf(-ax));
    return (x > 0.f) ? (x + l) : l;
}
__device__ __forceinline__ float to_tf32(float x) {
    uint32_t y;
    asm("cvt.rna.tf32.f32 %0, %1;" : "=r"(y) : "f"(x));
    return __uint_as_float(y);
}

// ---------------- mma wrappers ----------------
__device__ __forceinline__ void mma8(float* d, const uint32_t* a, const uint32_t* b) {
    asm volatile(
        "mma.sync.aligned.m16n8k8.row.col.f32.tf32.tf32.f32 "
        "{%0,%1,%2,%3}, {%4,%5,%6,%7}, {%8,%9}, {%0,%1,%2,%3};"
        : "+f"(d[0]), "+f"(d[1]), "+f"(d[2]), "+f"(d[3])
        : "r"(a[0]), "r"(a[1]), "r"(a[2]), "r"(a[3]), "r"(b[0]), "r"(b[1]));
}
__device__ __forceinline__ void mma16(float* d, uint32_t a0, uint32_t a1,
                                      uint32_t a2, uint32_t a3,
                                      uint32_t b0, uint32_t b1) {
    asm volatile(
        "mma.sync.aligned.m16n8k16.row.col.f32.bf16.bf16.f32 "
        "{%0,%1,%2,%3}, {%4,%5,%6,%7}, {%8,%9}, {%0,%1,%2,%3};"
        : "+f"(d[0]), "+f"(d[1]), "+f"(d[2]), "+f"(d[3])
        : "r"(a0), "r"(a1), "r"(a2), "r"(a3), "r"(b0), "r"(b1));
}

// =====================================================================
// Fused fixed-point loop kernels (bf16 MMA, W resident in SMEM)
// BM=32, BN=256, grid=512, 256 threads (8 warps as 2m x 4n, warp tile 16x64).
// State (v or z) lives in registers: each thread owns the same 32 cells
// for the C-fragment AND the A-operand (row,col)==(row,k).
// SMEM: Wsm 128KB (XOR-swizzled [n][k] bf16) + slots 64KB + Abuf 16.9KB.
// =====================================================================
#define FUS_SMEM 213504

// ---- shared helpers for fused kernels ----
__device__ __forceinline__ void load_W_smem(uint32_t* Wsm, const __nv_bfloat16* Wsrc,
                                            int tid) {
    const uint4* src = (const uint4*)Wsrc;
    for (int c = tid; c < 8192; c += 256) {
        int n = c >> 5;
        int w = (c & 31) * 4;
        uint4 d = src[c];
        *(uint4*)(Wsm + n * 128 + (w ^ ((n & 7) * 4))) = d;
    }
}

// One MMA pass: acc[8][4] += Abuf(32x256 bf16) @ Wsm(256x256 bf16 [n][k])
__device__ __forceinline__ void mma_pass(float acc[8][4], const uint32_t* Ab,
                                         const uint32_t* Wsm,
                                         int wm, int wn, int g, int t) {
#pragma unroll 4
    for (int k16 = 0; k16 < 16; k16++) {
        const int aw = (wm * 16 + g) * 132 + k16 * 8 + t;
        uint32_t a0 = Ab[aw];
        uint32_t a1 = Ab[aw + 8 * 132];
        uint32_t a2 = Ab[aw + 4];
        uint32_t a3 = Ab[aw + 8 * 132 + 4];
        const int w0 = (k16 * 8 + t)     ^ (4 * g);
        const int w1 = (k16 * 8 + t + 4) ^ (4 * g);
#pragma unroll
        for (int nj = 0; nj < 8; nj++) {
            const int nb = (wn * 64 + nj * 8 + g) * 128;
            mma16(acc[nj], a0, a1, a2, a3, Wsm[nb + w0], Wsm[nb + w1]);
        }
    }
}

// ---- v fixed point: ITERS x { v -= HG * (g(p,q,v) @ W^T) } ----
template <int ITERS>
__global__ void __launch_bounds__(256, 1)
vloop_f(float* __restrict__ v)
{
    extern __shared__ char sm[];
    uint32_t* Wsm = (uint32_t*)sm;                       // 131072 B
    float*    PQ  = (float*)(sm + 131072);               // [64][256] fp32
    uint32_t* Ab  = (uint32_t*)(sm + 131072 + 65536);    // 32 x 132 words

    const int tid = threadIdx.x, lane = tid & 31, warp = tid >> 5;
    const int wm = warp >> 2, wn = warp & 3;
    const int g = lane >> 2, t = lane & 3;
    const int m0 = blockIdx.x * 32;
    const int rowA = m0 + wm * 16 + g;
    const int colA = wn * 64 + t * 2;

    load_W_smem(Wsm, g_Wbf, tid);

    float vreg[8][4];
#pragma unroll
    for (int nj = 0; nj < 8; nj++) {
        const int c0 = colA + nj * 8;
        float2 a = *(const float2*)&v[rowA * DIM + c0];
        float2 b = *(const float2*)&v[(rowA + 8) * DIM + c0];
        vreg[nj][0] = a.x; vreg[nj][1] = a.y; vreg[nj][2] = b.x; vreg[nj][3] = b.y;
        float2 p0 = *(const float2*)&g_p[rowA * DIM + c0];
        float2 p1 = *(const float2*)&g_p[(rowA + 8) * DIM + c0];
        float2 q0 = *(const float2*)&g_q[rowA * DIM + c0];
        float2 q1 = *(const float2*)&g_q[(rowA + 8) * DIM + c0];
        PQ[(nj * 4 + 0) * 256 + tid] = p0.x;
        PQ[(nj * 4 + 1) * 256 + tid] = p0.y;
        PQ[(nj * 4 + 2) * 256 + tid] = p1.x;
        PQ[(nj * 4 + 3) * 256 + tid] = p1.y;
        PQ[(32 + nj * 4 + 0) * 256 + tid] = q0.x;
        PQ[(32 + nj * 4 + 1) * 256 + tid] = q0.y;
        PQ[(32 + nj * 4 + 2) * 256 + tid] = q1.x;
        PQ[(32 + nj * 4 + 3) * 256 + tid] = q1.y;
    }
    __syncthreads();

    for (int it = 0; it < ITERS; it++) {
        // phase1: build bf16 g into Abuf
#pragma unroll
        for (int nj = 0; nj < 8; nj++) {
#pragma unroll
            for (int h = 0; h < 2; h++) {
                float p0 = PQ[(nj * 4 + 2 * h)     * 256 + tid];
                float p1 = PQ[(nj * 4 + 2 * h + 1) * 256 + tid];
                float q0 = PQ[(32 + nj * 4 + 2 * h)     * 256 + tid];
                float q1 = PQ[(32 + nj * 4 + 2 * h + 1) * 256 + tid];
                float v0 = vreg[nj][2 * h], v1 = vreg[nj][2 * h + 1];
                float g0 = 0.5f * (p0 * v0 * v0 - q0);
                float g1 = 0.5f * (p1 * v1 * v1 - q1);
                __nv_bfloat162 hb = __floats2bfloat162_rn(g0, g1);
                *(__nv_bfloat162*)&Ab[(wm * 16 + g + 8 * h) * 132 + wn * 32 + nj * 4 + t] = hb;
            }
        }
        __syncthreads();
        // phase2: MMA
        float acc[8][4];
#pragma unroll
        for (int nj = 0; nj < 8; nj++)
#pragma unroll
            for (int c = 0; c < 4; c++) acc[nj][c] = 0.f;
        mma_pass(acc, Ab, Wsm, wm, wn, g, t);
        __syncthreads();
        // phase3: register update
#pragma unroll
        for (int nj = 0; nj < 8; nj++)
#pragma unroll
            for (int c = 0; c < 4; c++) vreg[nj][c] -= HG * acc[nj][c];
    }

#pragma unroll
    for (int nj = 0; nj < 8; nj++) {
        const int c0 = colA + nj * 8;
        *(float2*)&v[rowA * DIM + c0]       = make_float2(vreg[nj][0], vreg[nj][1]);
        *(float2*)&v[(rowA + 8) * DIM + c0] = make_float2(vreg[nj][2], vreg[nj][3]);
    }
}

// ---- z fixed point: 8 x { z += c + HG * softplus(z@W + bias) * vh } ----
__global__ void __launch_bounds__(256, 1)
zloop_f(const float* __restrict__ bias, float* __restrict__ z,
        const float* __restrict__ v)
{
    extern __shared__ char sm[];
    uint32_t* Wsm = (uint32_t*)sm;
    float*    CV  = (float*)(sm + 131072);               // c slots 0-31, vh slots 32-63
    uint32_t* Ab  = (uint32_t*)(sm + 131072 + 65536);

    const int tid = threadIdx.x, lane = tid & 31, warp = tid >> 5;
    const int wm = warp >> 2, wn = warp & 3;
    const int g = lane >> 2, t = lane & 3;
    const int m0 = blockIdx.x * 32;
    const int rowA = m0 + wm * 16 + g;
    const int colA = wn * 64 + t * 2;

    load_W_smem(Wsm, g_WTbf, tid);

    float zreg[8][4];
    float bx[8], by[8];
#pragma unroll
    for (int nj = 0; nj < 8; nj++) {
        const int c0 = colA + nj * 8;
        float2 a = *(const float2*)&z[rowA * DIM + c0];
        float2 b = *(const float2*)&z[(rowA + 8) * DIM + c0];
        zreg[nj][0] = a.x; zreg[nj][1] = a.y; zreg[nj][2] = b.x; zreg[nj][3] = b.y;
        float2 bb = *(const float2*)&bias[c0];
        bx[nj] = bb.x; by[nj] = bb.y;
        float2 c00 = *(const float2*)&g_c[rowA * DIM + c0];
        float2 c01 = *(const float2*)&g_c[(rowA + 8) * DIM + c0];
        float2 v00 = *(const float2*)&v[rowA * DIM + c0];
        float2 v01 = *(const float2*)&v[(rowA + 8) * DIM + c0];
        CV[(nj * 4 + 0) * 256 + tid] = c00.x;
        CV[(nj * 4 + 1) * 256 + tid] = c00.y;
        CV[(nj * 4 + 2) * 256 + tid] = c01.x;
        CV[(nj * 4 + 3) * 256 + tid] = c01.y;
        CV[(32 + nj * 4 + 0) * 256 + tid] = v00.x;
        CV[(32 + nj * 4 + 1) * 256 + tid] = v00.y;
        CV[(32 + nj * 4 + 2) * 256 + tid] = v01.x;
        CV[(32 + nj * 4 + 3) * 256 + tid] = v01.y;
    }
    __syncthreads();

    for (int it = 0; it < NFX; it++) {
        // phase1: bf16(z) into Abuf
#pragma unroll
        for (int nj = 0; nj < 8; nj++) {
#pragma unroll
            for (int h = 0; h < 2; h++) {
                __nv_bfloat162 hb =
                    __floats2bfloat162_rn(zreg[nj][2 * h], zreg[nj][2 * h + 1]);
                *(__nv_bfloat162*)&Ab[(wm * 16 + g + 8 * h) * 132 + wn * 32 + nj * 4 + t] = hb;
            }
        }
        __syncthreads();
        float acc[8][4];
#pragma unroll
        for (int nj = 0; nj < 8; nj++)
#pragma unroll
            for (int c = 0; c < 4; c++) acc[nj][c] = 0.f;
        mma_pass(acc, Ab, Wsm, wm, wn, g, t);
        __syncthreads();
        // phase3: z += c + HG*softplus(y+bias)*vh
#pragma unroll
        for (int nj = 0; nj < 8; nj++) {
#pragma unroll
            for (int h = 0; h < 2; h++) {
                float y0 = acc[nj][2 * h]     + bx[nj];
                float y1 = acc[nj][2 * h + 1] + by[nj];
                float c0 = CV[(nj * 4 + 2 * h)     * 256 + tid];
                float c1 = CV[(nj * 4 + 2 * h + 1) * 256 + tid];
                float h0 = CV[(32 + nj * 4 + 2 * h)     * 256 + tid];
                float h1 = CV[(32 + nj * 4 + 2 * h + 1) * 256 + tid];
                zreg[nj][2 * h]     += c0 + HG * softplus1(y0) * h0;
                zreg[nj][2 * h + 1] += c1 + HG * softplus1(y1) * h1;
            }
        }
    }

#pragma unroll
    for (int nj = 0; nj < 8; nj++) {
        const int c0 = colA + nj * 8;
        *(float2*)&z[rowA * DIM + c0]       = make_float2(zreg[nj][0], zreg[nj][1]);
        *(float2*)&z[(rowA + 8) * DIM + c0] = make_float2(zreg[nj][2], zreg[nj][3]);
    }
}

// =====================================================================
// tf32 single-GEMM kernel (validated round-4 code; modes A,U,C used)
// =====================================================================
#define MODE_A     0
#define MODE_VLOOP 1
#define MODE_U     2
#define MODE_C     3
#define MODE_Z     4

#define AS_STRIDE 36
#define BS_STRIDE 264

template <int MODE>
__global__ __launch_bounds__(256, 2)
void gemm_mma(const float* __restrict__ W, const float* __restrict__ bias,
              float* __restrict__ z, float* __restrict__ v)
{
    const float* __restrict__ Bop = (MODE == MODE_VLOOP || MODE == MODE_C)
                                        ? (const float*)g_WT : W;

    __shared__ float As[64][AS_STRIDE];
    __shared__ float Bs[32][BS_STRIDE];

    const int tid  = threadIdx.x;
    const int warp = tid >> 5;
    const int lane = tid & 31;
    const int wm   = warp >> 2;
    const int wn   = warp & 3;
    const int m0   = blockIdx.x * 64;

    float acc[2][8][4];
#pragma unroll
    for (int mr = 0; mr < 2; mr++)
#pragma unroll
        for (int nj = 0; nj < 8; nj++)
#pragma unroll
            for (int r = 0; r < 4; r++) acc[mr][nj][r] = 0.f;

    const int ak = tid & 31, ar = tid >> 5;
    const int bn = (tid & 63) * 4, bk = tid >> 6;

    const int r0 = lane >> 2;
    const int c0 = lane & 3;

    for (int kt = 0; kt < 8; kt++) {
        const int k0 = kt * 32;
#pragma unroll
        for (int ii = 0; ii < 8; ii++) {
            int row = ar + ii * 8;
            int gi  = (m0 + row) * DIM + k0 + ak;
            float a;
            if (MODE == MODE_VLOOP) {
                float vv = v[gi];
                a = 0.5f * (g_p[gi] * vv * vv - g_q[gi]);
            } else if (MODE == MODE_U) {
                a = v[gi];
            } else if (MODE == MODE_C) {
                a = g_u[gi];
            } else {
                a = z[gi];
            }
            As[row][ak] = to_tf32(a);
        }
#pragma unroll
        for (int ii = 0; ii < 8; ii++) {
            int kk = bk + ii * 4;
            float4 b4 = *(const float4*)&Bop[(k0 + kk) * DIM + bn];
            b4.x = to_tf32(b4.x); b4.y = to_tf32(b4.y);
            b4.z = to_tf32(b4.z); b4.w = to_tf32(b4.w);
            *(float4*)&Bs[kk][bn] = b4;
        }
        __syncthreads();

        const float* As_base = &As[wm * 32 + r0][c0];
        const float* Bs_base = &Bs[c0][wn * 64 + r0];
#pragma unroll
        for (int k8 = 0; k8 < 4; k8++) {
            const int kb = k8 * 8;
            uint32_t af[2][4];
#pragma unroll
            for (int mr = 0; mr < 2; mr++) {
                const float* p = As_base + (mr * 16) * AS_STRIDE + kb;
                af[mr][0] = __float_as_uint(p[0]);
                af[mr][1] = __float_as_uint(p[8 * AS_STRIDE]);
                af[mr][2] = __float_as_uint(p[4]);
                af[mr][3] = __float_as_uint(p[8 * AS_STRIDE + 4]);
            }
            uint32_t bf[8][2];
#pragma unroll
            for (int nj = 0; nj < 8; nj++) {
                const float* p = Bs_base + kb * BS_STRIDE + nj * 8;
                bf[nj][0] = __float_as_uint(p[0]);
                bf[nj][1] = __float_as_uint(p[4 * BS_STRIDE]);
            }
#pragma unroll
            for (int mr = 0; mr < 2; mr++)
#pragma unroll
                for (int nj = 0; nj < 8; nj++)
                    mma8(acc[mr][nj], af[mr], bf[nj]);
        }
        __syncthreads();
    }

#pragma unroll
    for (int mr = 0; mr < 2; mr++) {
#pragma unroll
        for (int nj = 0; nj < 8; nj++) {
            const int gc = wn * 64 + nj * 8 + 2 * c0;
            float2 bia = make_float2(0.f, 0.f);
            if (MODE == MODE_A || MODE == MODE_U || MODE == MODE_Z)
                bia = *(const float2*)&bias[gc];
#pragma unroll
            for (int hi = 0; hi < 2; hi++) {
                const int row = m0 + wm * 32 + mr * 16 + r0 + hi * 8;
                const int idx = row * DIM + gc;
                float y0 = acc[mr][nj][2 * hi]     + bia.x;
                float y1 = acc[mr][nj][2 * hi + 1] + bia.y;

                if (MODE == MODE_A) {
                    float sg0, ss0, sg1, ss1;
                    sig_sp(y0, sg0, ss0);
                    sig_sp(y1, sg1, ss1);
                    *(float2*)&g_p[idx] = make_float2(sg0, sg1);
                    *(float2*)&g_q[idx] = make_float2(__fdividef(sg0, ss0),
                                                      __fdividef(sg1, ss1));
                    *(float2*)&g_s[idx] = make_float2(ss0, ss1);
                } else if (MODE == MODE_VLOOP) {
                    float2 vv = *(float2*)&v[idx];
                    vv.x -= HG * y0;
                    vv.y -= HG * y1;
                    *(float2*)&v[idx] = vv;
                } else if (MODE == MODE_U) {
                    float sg0, ss0, sg1, ss1;
                    sig_sp(y0, sg0, ss0);
                    sig_sp(y1, sg1, ss1);
                    *(float2*)&g_u[idx] = make_float2(-0.5f * __fdividef(sg0, ss0),
                                                      -0.5f * __fdividef(sg1, ss1));
                } else if (MODE == MODE_C) {
                    float2 s2 = *(float2*)&g_s[idx];
                    float2 vv = *(float2*)&v[idx];
                    *(float2*)&g_c[idx] = make_float2(HG * (s2.x * vv.x + 2.f * y0),
                                                      HG * (s2.y * vv.y + 2.f * y1));
                } else {
                    float2 zz = *(float2*)&z[idx];
                    float2 c2 = *(float2*)&g_c[idx];
                    float2 vv = *(float2*)&v[idx];
                    zz.x += c2.x + HG * softplus1(y0) * vv.x;
                    zz.y += c2.y + HG * softplus1(y1) * vv.y;
                    *(float2*)&z[idx] = zz;
                }
            }
        }
    }
}

// ---------------- init / prep kernels ----------------
__global__ void init_k(float* __restrict__ z, float* __restrict__ v,
                       const float* __restrict__ z0, const float* __restrict__ v0)
{
    const float4* a = (const float4*)z0;
    const float4* b = (const float4*)v0;
    float4* zz = (float4*)z;
    float4* vv = (float4*)v;
    for (int i = blockIdx.x * blockDim.x + threadIdx.x; i < BD / 4;
         i += gridDim.x * blockDim.x) {
        zz[i] = a[i];
        vv[i] = b[i];
    }
}

__global__ void transpose_k(const float* __restrict__ W)
{
    __shared__ float t[32][33];
    const int bx = blockIdx.x * 32, by = blockIdx.y * 32;
    const int x = threadIdx.x, y = threadIdx.y;
#pragma unroll
    for (int j = 0; j < 32; j += 8)
        t[y + j][x] = W[(by + y + j) * DIM + bx + x];
    __syncthreads();
#pragma unroll
    for (int j = 0; j < 32; j += 8)
        g_WT[(bx + y + j) * DIM + by + x] = t[x][y + j];
}

__global__ void prep_bf(const float* __restrict__ W)
{
    int i = blockIdx.x * 256 + threadIdx.x;   // grid 256 -> 65536 threads
    float w = W[i];
    g_Wbf[i] = __float2bfloat16(w);
    int k = i >> 8, n = i & 255;
    g_WTbf[n * 256 + k] = __float2bfloat16(w);
}

// ---------------- host launch sequence (graph-capturable) ----------------
extern "C" void kernel_launch(void* const* d_in, const int* in_sizes, int n_in,
                              void* d_out, int out_size)
{
    const float* z0 = nullptr; const float* v0 = nullptr;
    const float* W  = nullptr; const float* bias = nullptr;
    for (int i = 0; i < n_in; i++) {
        if (in_sizes[i] == BD) {
            if (!z0) z0 = (const float*)d_in[i];
            else if (!v0) v0 = (const float*)d_in[i];
        } else if (in_sizes[i] == DIM * DIM) {
            W = (const float*)d_in[i];
        } else if (in_sizes[i] == DIM) {
            bias = (const float*)d_in[i];
        }
    }

    float* z = (float*)d_out;
    float* v = z + BD;

    cudaFuncSetAttribute(vloop_f<8>, cudaFuncAttributeMaxDynamicSharedMemorySize, FUS_SMEM);
    cudaFuncSetAttribute(vloop_f<1>, cudaFuncAttributeMaxDynamicSharedMemorySize, FUS_SMEM);
    cudaFuncSetAttribute(zloop_f,    cudaFuncAttributeMaxDynamicSharedMemorySize, FUS_SMEM);

    init_k<<<1024, 256>>>(z, v, z0, v0);
    transpose_k<<<dim3(8, 8), dim3(32, 8)>>>(W);
    prep_bf<<<256, 256>>>(W);

    const dim3 gs(B_ROWS / 64), ts(256);
    const dim3 gf(B_ROWS / 32);

    gemm_mma<MODE_A><<<gs, ts>>>(W, bias, z, v);

    for (int s = 0; s < LSTEPS; s++) {
        vloop_f<8><<<gf, 256, FUS_SMEM>>>(v);
        gemm_mma<MODE_U><<<gs, ts>>>(W, bias, z, v);
        gemm_mma<MODE_C><<<gs, ts>>>(W, bias, z, v);
        zloop_f<<<gf, 256, FUS_SMEM>>>(bias, z, v);
        gemm_mma<MODE_A><<<gs, ts>>>(W, bias, z, v);
        vloop_f<1><<<gf, 256, FUS_SMEM>>>(v);
    }
}

// round 7
// speedup vs baseline: 3.6197x; 1.1566x over previous
#include <cuda_runtime.h>
#include <cuda_bf16.h>
#include <cstdint>

#define B_ROWS 16384
#define DIM    256
#define BD     (B_ROWS * DIM)
#define LSTEPS 6
#define HG     0.005f   /* GAMMA / 2 */

// ---------------- device scratch ----------------
__device__ float g_p[BD];
__device__ float g_q[BD];
__device__ float g_s[BD];
__device__ float g_c[BD];
__device__ __nv_bfloat16 g_Wbf[DIM * DIM];   // W row-major  ([n][k] B-operand: g@W^T, u@W^T)
__device__ __nv_bfloat16 g_WTbf[DIM * DIM];  // W^T row-major ([n][k] B-operand: x@W)

// ---------------- stable transcendentals ----------------
__device__ __forceinline__ void sig_sp(float x, float &sg, float &sp) {
    float ax  = fabsf(x);
    float e   = __expf(-ax);
    float l   = log1pf(e);
    sp        = (x > 0.f) ? (x + l) : l;
    float inv = __fdividef(1.f, 1.f + e);
    sg        = (x > 0.f) ? inv : (1.f - inv);
}
__device__ __forceinline__ float softplus1(float x) {
    float ax = fabsf(x);
    float l  = log1pf(__expf(-ax));
    return (x > 0.f) ? (x + l) : l;
}
__device__ __forceinline__ float to_tf32(float x) {
    uint32_t y;
    asm("cvt.rna.tf32.f32 %0, %1;" : "=r"(y) : "f"(x));
    return __uint_as_float(y);
}

// ---------------- mma wrappers ----------------
__device__ __forceinline__ void mma8(float* d, const uint32_t* a, const uint32_t* b) {
    asm volatile(
        "mma.sync.aligned.m16n8k8.row.col.f32.tf32.tf32.f32 "
        "{%0,%1,%2,%3}, {%4,%5,%6,%7}, {%8,%9}, {%0,%1,%2,%3};"
        : "+f"(d[0]), "+f"(d[1]), "+f"(d[2]), "+f"(d[3])
        : "r"(a[0]), "r"(a[1]), "r"(a[2]), "r"(a[3]), "r"(b[0]), "r"(b[1]));
}
__device__ __forceinline__ void mma16(float* d, uint32_t a0, uint32_t a1,
                                      uint32_t a2, uint32_t a3,
                                      uint32_t b0, uint32_t b1) {
    asm volatile(
        "mma.sync.aligned.m16n8k16.row.col.f32.bf16.bf16.f32 "
        "{%0,%1,%2,%3}, {%4,%5,%6,%7}, {%8,%9}, {%0,%1,%2,%3};"
        : "+f"(d[0]), "+f"(d[1]), "+f"(d[2]), "+f"(d[3])
        : "r"(a0), "r"(a1), "r"(a2), "r"(a3), "r"(b0), "r"(b1));
}

// =====================================================================
// Phase kernels: BM=64, BN=256, grid 256, 512 threads (16 warps 4m x 4n,
// warp tile 16x64). SMEM: Wsm 128K (swizzled [n][k] bf16) + slots 64K +
// Abuf 33.8K = 230400 B. Per-thread cell ownership identical for the
// C-fragment and the A-operand (rows rowA/rowA+8, cols colA+nj*8{,+1}).
// =====================================================================
#define NTH      512
#define FUS_SMEM 230400

__device__ __forceinline__ void load_W_smem(uint32_t* Wsm,
                                            const __nv_bfloat16* Wsrc, int tid) {
    const uint4* src = (const uint4*)Wsrc;
    for (int c = tid; c < 8192; c += NTH) {
        int n = c >> 5;
        int w = (c & 31) * 4;
        uint4 d = src[c];
        *(uint4*)(Wsm + n * 128 + (w ^ ((n & 7) * 4))) = d;
    }
}

// acc[8][4] += Abuf(64x256 bf16) @ Wsm(256x256 bf16 [n][k])  (per-warp 16x64 tile)
__device__ __forceinline__ void mma_pass(float acc[8][4], const uint32_t* Ab,
                                         const uint32_t* Wsm,
                                         int wm, int wn, int g, int t) {
#pragma unroll 4
    for (int k16 = 0; k16 < 16; k16++) {
        const int aw = (wm * 16 + g) * 132 + k16 * 8 + t;
        uint32_t a0 = Ab[aw];
        uint32_t a1 = Ab[aw + 8 * 132];
        uint32_t a2 = Ab[aw + 4];
        uint32_t a3 = Ab[aw + 8 * 132 + 4];
        const int w0 = (k16 * 8 + t)     ^ (4 * g);
        const int w1 = (k16 * 8 + t + 4) ^ (4 * g);
#pragma unroll
        for (int nj = 0; nj < 8; nj++) {
            const int nb = (wn * 64 + nj * 8 + g) * 128;
            mma16(acc[nj], a0, a1, a2, a3, Wsm[nb + w0], Wsm[nb + w1]);
        }
    }
}

__device__ __forceinline__ void store_A(uint32_t* Ab, const float (*x)[4],
                                        int wm, int wn, int g, int t) {
#pragma unroll
    for (int nj = 0; nj < 8; nj++)
#pragma unroll
        for (int h = 0; h < 2; h++) {
            __nv_bfloat162 hb =
                __floats2bfloat162_rn(x[nj][2 * h], x[nj][2 * h + 1]);
            *(__nv_bfloat162*)&Ab[(wm * 16 + g + 8 * h) * 132 + wn * 32 + nj * 4 + t] = hb;
        }
}

// ---- phaseV: vloop x8  ->  U (u from a(vh))  ->  C (c = HG(s*vh + 2r)) ----
__global__ void __launch_bounds__(NTH, 1)
phaseV(const float* __restrict__ bias, float* __restrict__ v)
{
    extern __shared__ char sm[];
    uint32_t*      Wsm = (uint32_t*)sm;
    __nv_bfloat16* PQ  = (__nv_bfloat16*)(sm + 131072);   // p slots 0-31, q 32-63
    uint32_t*      Ab  = (uint32_t*)(sm + 131072 + 65536);

    const int tid = threadIdx.x, lane = tid & 31, warp = tid >> 5;
    const int wm = warp >> 2, wn = warp & 3;
    const int g = lane >> 2, t = lane & 3;
    const int m0   = blockIdx.x * 64;
    const int rowA = m0 + wm * 16 + g;
    const int colA = wn * 64 + 2 * t;

    load_W_smem(Wsm, g_Wbf, tid);

    float vreg[8][4];
#pragma unroll
    for (int nj = 0; nj < 8; nj++) {
        const int c0 = colA + nj * 8;
        float2 a = *(const float2*)&v[rowA * DIM + c0];
        float2 b = *(const float2*)&v[(rowA + 8) * DIM + c0];
        vreg[nj][0] = a.x; vreg[nj][1] = a.y; vreg[nj][2] = b.x; vreg[nj][3] = b.y;
        float2 p0 = *(const float2*)&g_p[rowA * DIM + c0];
        float2 p1 = *(const float2*)&g_p[(rowA + 8) * DIM + c0];
        float2 q0 = *(const float2*)&g_q[rowA * DIM + c0];
        float2 q1 = *(const float2*)&g_q[(rowA + 8) * DIM + c0];
        PQ[(nj * 4 + 0) * NTH + tid] = __float2bfloat16(p0.x);
        PQ[(nj * 4 + 1) * NTH + tid] = __float2bfloat16(p0.y);
        PQ[(nj * 4 + 2) * NTH + tid] = __float2bfloat16(p1.x);
        PQ[(nj * 4 + 3) * NTH + tid] = __float2bfloat16(p1.y);
        PQ[(32 + nj * 4 + 0) * NTH + tid] = __float2bfloat16(q0.x);
        PQ[(32 + nj * 4 + 1) * NTH + tid] = __float2bfloat16(q0.y);
        PQ[(32 + nj * 4 + 2) * NTH + tid] = __float2bfloat16(q1.x);
        PQ[(32 + nj * 4 + 3) * NTH + tid] = __float2bfloat16(q1.y);
    }
    __syncthreads();

    for (int it = 0; it < 8; it++) {
#pragma unroll
        for (int nj = 0; nj < 8; nj++)
#pragma unroll
            for (int h = 0; h < 2; h++) {
                float p0 = __bfloat162float(PQ[(nj * 4 + 2 * h)     * NTH + tid]);
                float p1 = __bfloat162float(PQ[(nj * 4 + 2 * h + 1) * NTH + tid]);
                float q0 = __bfloat162float(PQ[(32 + nj * 4 + 2 * h)     * NTH + tid]);
                float q1 = __bfloat162float(PQ[(32 + nj * 4 + 2 * h + 1) * NTH + tid]);
                float v0 = vreg[nj][2 * h], v1 = vreg[nj][2 * h + 1];
                __nv_bfloat162 hb = __floats2bfloat162_rn(
                    0.5f * (p0 * v0 * v0 - q0), 0.5f * (p1 * v1 * v1 - q1));
                *(__nv_bfloat162*)&Ab[(wm * 16 + g + 8 * h) * 132 + wn * 32 + nj * 4 + t] = hb;
            }
        __syncthreads();
        float acc[8][4];
#pragma unroll
        for (int nj = 0; nj < 8; nj++)
#pragma unroll
            for (int c = 0; c < 4; c++) acc[nj][c] = 0.f;
        mma_pass(acc, Ab, Wsm, wm, wn, g, t);
        __syncthreads();
#pragma unroll
        for (int nj = 0; nj < 8; nj++)
#pragma unroll
            for (int c = 0; c < 4; c++) vreg[nj][c] -= HG * acc[nj][c];
    }

    // ---- U: y = vh@W + bias  (B switches to WTbf) ----
    load_W_smem(Wsm, g_WTbf, tid);
    store_A(Ab, vreg, wm, wn, g, t);
    float bx[8], by[8];
#pragma unroll
    for (int nj = 0; nj < 8; nj++) {
        float2 bb = *(const float2*)&bias[colA + nj * 8];
        bx[nj] = bb.x; by[nj] = bb.y;
    }
    __syncthreads();
    {
        float acc[8][4];
#pragma unroll
        for (int nj = 0; nj < 8; nj++)
#pragma unroll
            for (int c = 0; c < 4; c++) acc[nj][c] = 0.f;
        mma_pass(acc, Ab, Wsm, wm, wn, g, t);
        __syncthreads();
        // u = -0.5*sigma/softplus -> Ab  (post-mma sync passed: Ab safe)
#pragma unroll
        for (int nj = 0; nj < 8; nj++)
#pragma unroll
            for (int h = 0; h < 2; h++) {
                float y0 = acc[nj][2 * h]     + bx[nj];
                float y1 = acc[nj][2 * h + 1] + by[nj];
                float sg0, ss0, sg1, ss1;
                sig_sp(y0, sg0, ss0);
                sig_sp(y1, sg1, ss1);
                __nv_bfloat162 hb = __floats2bfloat162_rn(
                    -0.5f * __fdividef(sg0, ss0), -0.5f * __fdividef(sg1, ss1));
                *(__nv_bfloat162*)&Ab[(wm * 16 + g + 8 * h) * 132 + wn * 32 + nj * 4 + t] = hb;
            }
    }
    // ---- C: r = u@W^T  (B back to Wbf);  c = HG*(s*vh + 2r) ----
    load_W_smem(Wsm, g_Wbf, tid);
    __syncthreads();
    {
        float acc[8][4];
#pragma unroll
        for (int nj = 0; nj < 8; nj++)
#pragma unroll
            for (int c = 0; c < 4; c++) acc[nj][c] = 0.f;
        mma_pass(acc, Ab, Wsm, wm, wn, g, t);
        __syncthreads();
#pragma unroll
        for (int nj = 0; nj < 8; nj++) {
            const int c0 = colA + nj * 8;
            float2 s0 = *(const float2*)&g_s[rowA * DIM + c0];
            float2 s1 = *(const float2*)&g_s[(rowA + 8) * DIM + c0];
            *(float2*)&g_c[rowA * DIM + c0] =
                make_float2(HG * (s0.x * vreg[nj][0] + 2.f * acc[nj][0]),
                            HG * (s0.y * vreg[nj][1] + 2.f * acc[nj][1]));
            *(float2*)&g_c[(rowA + 8) * DIM + c0] =
                make_float2(HG * (s1.x * vreg[nj][2] + 2.f * acc[nj][2]),
                            HG * (s1.y * vreg[nj][3] + 2.f * acc[nj][3]));
            *(float2*)&v[rowA * DIM + c0]       = make_float2(vreg[nj][0], vreg[nj][1]);
            *(float2*)&v[(rowA + 8) * DIM + c0] = make_float2(vreg[nj][2], vreg[nj][3]);
        }
    }
}

// ---- phaseZ: zloop x8 -> A (p,q,s at z_new) -> vhalf ----
__global__ void __launch_bounds__(NTH, 1)
phaseZ(const float* __restrict__ bias, float* __restrict__ z, float* __restrict__ v)
{
    extern __shared__ char sm[];
    uint32_t*      Wsm = (uint32_t*)sm;
    float*         CS  = (float*)(sm + 131072);           // c fp32, slots 0-31
    __nv_bfloat16* PQ  = (__nv_bfloat16*)(sm + 131072);   // overlay after zloop
    uint32_t*      Ab  = (uint32_t*)(sm + 131072 + 65536);

    const int tid = threadIdx.x, lane = tid & 31, warp = tid >> 5;
    const int wm = warp >> 2, wn = warp & 3;
    const int g = lane >> 2, t = lane & 3;
    const int m0   = blockIdx.x * 64;
    const int rowA = m0 + wm * 16 + g;
    const int colA = wn * 64 + 2 * t;

    load_W_smem(Wsm, g_WTbf, tid);

    float zreg[8][4], vh[8][4], bx[8], by[8];
#pragma unroll
    for (int nj = 0; nj < 8; nj++) {
        const int c0 = colA + nj * 8;
        float2 a = *(const float2*)&z[rowA * DIM + c0];
        float2 b = *(const float2*)&z[(rowA + 8) * DIM + c0];
        zreg[nj][0] = a.x; zreg[nj][1] = a.y; zreg[nj][2] = b.x; zreg[nj][3] = b.y;
        float2 va = *(const float2*)&v[rowA * DIM + c0];
        float2 vb = *(const float2*)&v[(rowA + 8) * DIM + c0];
        vh[nj][0] = va.x; vh[nj][1] = va.y; vh[nj][2] = vb.x; vh[nj][3] = vb.y;
        float2 bb = *(const float2*)&bias[c0];
        bx[nj] = bb.x; by[nj] = bb.y;
        float2 ca = *(const float2*)&g_c[rowA * DIM + c0];
        float2 cb = *(const float2*)&g_c[(rowA + 8) * DIM + c0];
        CS[(nj * 4 + 0) * NTH + tid] = ca.x;
        CS[(nj * 4 + 1) * NTH + tid] = ca.y;
        CS[(nj * 4 + 2) * NTH + tid] = cb.x;
        CS[(nj * 4 + 3) * NTH + tid] = cb.y;
    }
    __syncthreads();

    for (int it = 0; it < 8; it++) {
        store_A(Ab, zreg, wm, wn, g, t);
        __syncthreads();
        float acc[8][4];
#pragma unroll
        for (int nj = 0; nj < 8; nj++)
#pragma unroll
            for (int c = 0; c < 4; c++) acc[nj][c] = 0.f;
        mma_pass(acc, Ab, Wsm, wm, wn, g, t);
        __syncthreads();
#pragma unroll
        for (int nj = 0; nj < 8; nj++)
#pragma unroll
            for (int h = 0; h < 2; h++) {
                float y0 = acc[nj][2 * h]     + bx[nj];
                float y1 = acc[nj][2 * h + 1] + by[nj];
                float c0 = CS[(nj * 4 + 2 * h)     * NTH + tid];
                float c1 = CS[(nj * 4 + 2 * h + 1) * NTH + tid];
                zreg[nj][2 * h]     += c0 + HG * softplus1(y0) * vh[nj][2 * h];
                zreg[nj][2 * h + 1] += c1 + HG * softplus1(y1) * vh[nj][2 * h + 1];
            }
    }

    // ---- A phase: y = z_new@W + bias  (same B operand, no reload) ----
    store_A(Ab, zreg, wm, wn, g, t);
    __syncthreads();
    {
        float acc[8][4];
#pragma unroll
        for (int nj = 0; nj < 8; nj++)
#pragma unroll
            for (int c = 0; c < 4; c++) acc[nj][c] = 0.f;
        mma_pass(acc, Ab, Wsm, wm, wn, g, t);
        __syncthreads();
        // p,q,s: store to gmem (next phaseV) and p,q to slots (vhalf below)
#pragma unroll
        for (int nj = 0; nj < 8; nj++)
#pragma unroll
            for (int h = 0; h < 2; h++) {
                const int c0 = colA + nj * 8;
                const int idx = (rowA + 8 * h) * DIM + c0;
                float y0 = acc[nj][2 * h]     + bx[nj];
                float y1 = acc[nj][2 * h + 1] + by[nj];
                float sg0, ss0, sg1, ss1;
                sig_sp(y0, sg0, ss0);
                sig_sp(y1, sg1, ss1);
                float q0 = __fdividef(sg0, ss0);
                float q1 = __fdividef(sg1, ss1);
                *(float2*)&g_p[idx] = make_float2(sg0, sg1);
                *(float2*)&g_q[idx] = make_float2(q0, q1);
                *(float2*)&g_s[idx] = make_float2(ss0, ss1);
                PQ[(nj * 4 + 2 * h)     * NTH + tid] = __float2bfloat16(sg0);
                PQ[(nj * 4 + 2 * h + 1) * NTH + tid] = __float2bfloat16(sg1);
                PQ[(32 + nj * 4 + 2 * h)     * NTH + tid] = __float2bfloat16(q0);
                PQ[(32 + nj * 4 + 2 * h + 1) * NTH + tid] = __float2bfloat16(q1);
            }
    }
    // ---- vhalf: one v iteration with fresh p,q (vh already in registers) ----
    load_W_smem(Wsm, g_Wbf, tid);
    __syncthreads();
#pragma unroll
    for (int nj = 0; nj < 8; nj++)
#pragma unroll
        for (int h = 0; h < 2; h++) {
            float p0 = __bfloat162float(PQ[(nj * 4 + 2 * h)     * NTH + tid]);
            float p1 = __bfloat162float(PQ[(nj * 4 + 2 * h + 1) * NTH + tid]);
            float q0 = __bfloat162float(PQ[(32 + nj * 4 + 2 * h)     * NTH + tid]);
            float q1 = __bfloat162float(PQ[(32 + nj * 4 + 2 * h + 1) * NTH + tid]);
            float v0 = vh[nj][2 * h], v1 = vh[nj][2 * h + 1];
            __nv_bfloat162 hb = __floats2bfloat162_rn(
                0.5f * (p0 * v0 * v0 - q0), 0.5f * (p1 * v1 * v1 - q1));
            *(__nv_bfloat162*)&Ab[(wm * 16 + g + 8 * h) * 132 + wn * 32 + nj * 4 + t] = hb;
        }
    __syncthreads();
    {
        float acc[8][4];
#pragma unroll
        for (int nj = 0; nj < 8; nj++)
#pragma unroll
            for (int c = 0; c < 4; c++) acc[nj][c] = 0.f;
        mma_pass(acc, Ab, Wsm, wm, wn, g, t);
        __syncthreads();
#pragma unroll
        for (int nj = 0; nj < 8; nj++) {
            const int c0 = colA + nj * 8;
#pragma unroll
            for (int c = 0; c < 4; c++) vh[nj][c] -= HG * acc[nj][c];
            *(float2*)&v[rowA * DIM + c0]       = make_float2(vh[nj][0], vh[nj][1]);
            *(float2*)&v[(rowA + 8) * DIM + c0] = make_float2(vh[nj][2], vh[nj][3]);
            *(float2*)&z[rowA * DIM + c0]       = make_float2(zreg[nj][0], zreg[nj][1]);
            *(float2*)&z[(rowA + 8) * DIM + c0] = make_float2(zreg[nj][2], zreg[nj][3]);
        }
    }
}

// =====================================================================
// Initial A: tf32 single GEMM (validated round-4 code, MODE_A only)
// =====================================================================
#define AS_STRIDE 36
#define BS_STRIDE 264

__global__ __launch_bounds__(256, 2)
void gemmA(const float* __restrict__ W, const float* __restrict__ bias,
           const float* __restrict__ z)
{
    __shared__ float As[64][AS_STRIDE];
    __shared__ float Bs[32][BS_STRIDE];

    const int tid  = threadIdx.x;
    const int warp = tid >> 5;
    const int lane = tid & 31;
    const int wm   = warp >> 2;
    const int wn   = warp & 3;
    const int m0   = blockIdx.x * 64;

    float acc[2][8][4];
#pragma unroll
    for (int mr = 0; mr < 2; mr++)
#pragma unroll
        for (int nj = 0; nj < 8; nj++)
#pragma unroll
            for (int r = 0; r < 4; r++) acc[mr][nj][r] = 0.f;

    const int ak = tid & 31, ar = tid >> 5;
    const int bn = (tid & 63) * 4, bk = tid >> 6;
    const int r0 = lane >> 2;
    const int c0 = lane & 3;

    for (int kt = 0; kt < 8; kt++) {
        const int k0 = kt * 32;
#pragma unroll
        for (int ii = 0; ii < 8; ii++) {
            int row = ar + ii * 8;
            As[row][ak] = to_tf32(z[(m0 + row) * DIM + k0 + ak]);
        }
#pragma unroll
        for (int ii = 0; ii < 8; ii++) {
            int kk = bk + ii * 4;
            float4 b4 = *(const float4*)&W[(k0 + kk) * DIM + bn];
            b4.x = to_tf32(b4.x); b4.y = to_tf32(b4.y);
            b4.z = to_tf32(b4.z); b4.w = to_tf32(b4.w);
            *(float4*)&Bs[kk][bn] = b4;
        }
        __syncthreads();

        const float* As_base = &As[wm * 32 + r0][c0];
        const float* Bs_base = &Bs[c0][wn * 64 + r0];
#pragma unroll
        for (int k8 = 0; k8 < 4; k8++) {
            const int kb = k8 * 8;
            uint32_t af[2][4];
#pragma unroll
            for (int mr = 0; mr < 2; mr++) {
                const float* p = As_base + (mr * 16) * AS_STRIDE + kb;
                af[mr][0] = __float_as_uint(p[0]);
                af[mr][1] = __float_as_uint(p[8 * AS_STRIDE]);
                af[mr][2] = __float_as_uint(p[4]);
                af[mr][3] = __float_as_uint(p[8 * AS_STRIDE + 4]);
            }
            uint32_t bf[8][2];
#pragma unroll
            for (int nj = 0; nj < 8; nj++) {
                const float* p = Bs_base + kb * BS_STRIDE + nj * 8;
                bf[nj][0] = __float_as_uint(p[0]);
                bf[nj][1] = __float_as_uint(p[4 * BS_STRIDE]);
            }
#pragma unroll
            for (int mr = 0; mr < 2; mr++)
#pragma unroll
                for (int nj = 0; nj < 8; nj++)
                    mma8(acc[mr][nj], af[mr], bf[nj]);
        }
        __syncthreads();
    }

#pragma unroll
    for (int mr = 0; mr < 2; mr++) {
#pragma unroll
        for (int nj = 0; nj < 8; nj++) {
            const int gc = wn * 64 + nj * 8 + 2 * c0;
            float2 bia = *(const float2*)&bias[gc];
#pragma unroll
            for (int hi = 0; hi < 2; hi++) {
                const int row = m0 + wm * 32 + mr * 16 + r0 + hi * 8;
                const int idx = row * DIM + gc;
                float y0 = acc[mr][nj][2 * hi]     + bia.x;
                float y1 = acc[mr][nj][2 * hi + 1] + bia.y;
                float sg0, ss0, sg1, ss1;
                sig_sp(y0, sg0, ss0);
                sig_sp(y1, sg1, ss1);
                *(float2*)&g_p[idx] = make_float2(sg0, sg1);
                *(float2*)&g_q[idx] = make_float2(__fdividef(sg0, ss0),
                                                  __fdividef(sg1, ss1));
                *(float2*)&g_s[idx] = make_float2(ss0, ss1);
            }
        }
    }
}

// ---------------- init / prep ----------------
__global__ void init_k(float* __restrict__ z, float* __restrict__ v,
                       const float* __restrict__ z0, const float* __restrict__ v0)
{
    const float4* a = (const float4*)z0;
    const float4* b = (const float4*)v0;
    float4* zz = (float4*)z;
    float4* vv = (float4*)v;
    for (int i = blockIdx.x * blockDim.x + threadIdx.x; i < BD / 4;
         i += gridDim.x * blockDim.x) {
        zz[i] = a[i];
        vv[i] = b[i];
    }
}

__global__ void prep_bf(const float* __restrict__ W)
{
    int i = blockIdx.x * 256 + threadIdx.x;   // 65536 threads
    float w = W[i];
    g_Wbf[i] = __float2bfloat16(w);
    int k = i >> 8, n = i & 255;
    g_WTbf[n * 256 + k] = __float2bfloat16(w);
}

// ---------------- host launch sequence (graph-capturable) ----------------
extern "C" void kernel_launch(void* const* d_in, const int* in_sizes, int n_in,
                              void* d_out, int out_size)
{
    const float* z0 = nullptr; const float* v0 = nullptr;
    const float* W  = nullptr; const float* bias = nullptr;
    for (int i = 0; i < n_in; i++) {
        if (in_sizes[i] == BD) {
            if (!z0) z0 = (const float*)d_in[i];
            else if (!v0) v0 = (const float*)d_in[i];
        } else if (in_sizes[i] == DIM * DIM) {
            W = (const float*)d_in[i];
        } else if (in_sizes[i] == DIM) {
            bias = (const float*)d_in[i];
        }
    }

    float* z = (float*)d_out;
    float* v = z + BD;

    cudaFuncSetAttribute(phaseV, cudaFuncAttributeMaxDynamicSharedMemorySize, FUS_SMEM);
    cudaFuncSetAttribute(phaseZ, cudaFuncAttributeMaxDynamicSharedMemorySize, FUS_SMEM);

    init_k<<<1024, 256>>>(z, v, z0, v0);
    prep_bf<<<256, 256>>>(W);

    gemmA<<<B_ROWS / 64, 256>>>(W, bias, z);

    for (int s = 0; s < LSTEPS; s++) {
        phaseV<<<B_ROWS / 64, NTH, FUS_SMEM>>>(bias, v);
        phaseZ<<<B_ROWS / 64, NTH, FUS_SMEM>>>(bias, z, v);
    }
}